// round 12
// baseline (speedup 1.0000x reference)
#include <cuda_runtime.h>
#include <cuda_fp16.h>

// Problem constants (fixed by the reference)
#define VV   4096                 // vocab
#define MM   4                    // markov order
#define BB   8
#define LL   2048
#define FAN  (MM * (VV + 1))      // 16388
#define NPOS (BB * LL)            // 16384

#define VC   1024                 // vocab chunk; one slab = FAN*VC*2B = 33.5 MB
#define NCH  (VV / VC)            // 4 chunks

#define NSUB 4                    // subtiles per transpose block (along fan_in)
#define CT   (NSUB * 32)          // 128 fan_in columns per block
#define CMAIN 16384               // fan_in covered by main transpose tiles

#define GGRID 888                 // persistent gather grid: 6 CTAs x 148 SMs

// TWO slabs (67 MB total), double-buffered so two chunks can be produced in
// one launch and consumed in one launch. Both stay L2-resident between the
// paired T and G launches. Table-0 rows carry the fp32 bias folded in.
__device__ __half g_slab[2][(size_t)FAN * VC];

// ---------------------------------------------------------------------------
// Kernel 1: paired transpose+quantize. For z = 0,1: W rows
// [(2*cpair+z)*VC, +VC) x all FAN cols -> g_slab[z] [FAN][VC] fp16.
// Proven 4x 32x33 scalar-smem subtile scheme (conflict-free both phases).
// W reads use __ldcs (evict-first) to protect the slabs in L2.
// grid = (129, 32, 2), block (8,32). blockIdx.x == 128 -> remainder fan rows.
// ---------------------------------------------------------------------------
__global__ __launch_bounds__(256)
void ngram_transpose_pair(const float* __restrict__ W,
                          const float* __restrict__ bias, int cpair) {
    const int tx = threadIdx.x;       // 0..7
    const int ty = threadIdx.y;       // 0..31
    const int z  = blockIdx.z;        // slab / sub-chunk select
    const int v0 = (cpair * 2 + z) * VC;
    __half* slab = g_slab[z];

    if (blockIdx.x == CMAIN / CT) {
        // Remainder rows cc = 16384..16387 (table 3: no bias) for this slice.
        const int t = ty * 8 + tx;    // 0..255
        if (t < 4 * 32) {
            const int r  = t >> 5;    // 0..3
            const int v  = t & 31;
            const int vl = blockIdx.y * 32 + v;       // local vocab in chunk
            slab[(size_t)(CMAIN + r) * VC + vl] =
                __float2half_rn(W[(size_t)(v0 + vl) * FAN + CMAIN + r]);
        }
        return;
    }

    __shared__ float tile[NSUB][32][33];

    const int c0  = blockIdx.x * CT;       // fan_in origin
    const int vl0 = blockIdx.y * 32;       // local vocab origin within chunk

    // Load phase: 4 independent float4 streaming reads, scalar smem writes.
    float4 w4[NSUB];
    const float4* wrow = reinterpret_cast<const float4*>(
        &W[(size_t)(v0 + vl0 + ty) * FAN + c0 + tx * 4]);
    #pragma unroll
    for (int s = 0; s < NSUB; s++)
        w4[s] = __ldcs(wrow + s * 8);      // evict-first: don't pollute L2
    #pragma unroll
    for (int s = 0; s < NSUB; s++) {
        tile[s][ty][tx * 4 + 0] = w4[s].x;
        tile[s][ty][tx * 4 + 1] = w4[s].y;
        tile[s][ty][tx * 4 + 2] = w4[s].z;
        tile[s][ty][tx * 4 + 3] = w4[s].w;
    }
    __syncthreads();

    // Store phase: scalar smem reads, optional bias fold (exact fp32 add),
    // cvt to fp16, 8-byte slab writes (write-back -> dirty lines live in L2).
    const bool foldblk = (c0 < VV + 1);
    float4 bb = make_float4(0.f, 0.f, 0.f, 0.f);
    if (foldblk)
        bb = *reinterpret_cast<const float4*>(&bias[v0 + vl0 + tx * 4]);

    #pragma unroll
    for (int s = 0; s < NSUB; s++) {
        const int cc = c0 + s * 32 + ty;
        float x0 = tile[s][tx * 4 + 0][ty];
        float x1 = tile[s][tx * 4 + 1][ty];
        float x2 = tile[s][tx * 4 + 2][ty];
        float x3 = tile[s][tx * 4 + 3][ty];
        if (foldblk && cc < VV + 1) {      // table 0: fold bias
            x0 += bb.x; x1 += bb.y; x2 += bb.z; x3 += bb.w;
        }
        const __half2 p0 = __floats2half2_rn(x0, x1);
        const __half2 p1 = __floats2half2_rn(x2, x3);
        uint2 o;
        o.x = *reinterpret_cast<const unsigned int*>(&p0);
        o.y = *reinterpret_cast<const unsigned int*>(&p1);
        *reinterpret_cast<uint2*>(&slab[(size_t)cc * VC + vl0 + tx * 4]) = o;
    }
}

// ---------------------------------------------------------------------------
// Kernel 2: paired persistent gather-sum, warp-per-position.
// grid = GGRID = 888 (one fully-resident wave at 6 CTAs/SM), block 256.
// Work-stride loop over 4096 items = (2 chunks) x (2048 position-blocks):
// zero wave-quantization tail. Inner loop: 4 iters of 4 independent LDG.128
// (slab, L2 hits) + 8 HADD2 + cvt + fp32 finish + 2 streaming STG.128.
// ---------------------------------------------------------------------------
__global__ __launch_bounds__(256, 6)
void ngram_gather_pair(const int* __restrict__ idx,
                       float* __restrict__ out, int cpair) {
    const int warp = threadIdx.x >> 5;
    const int lane = threadIdx.x & 31;

    for (int item = blockIdx.x; item < 2 * (NPOS / 8); item += GGRID) {
        const int half  = item >> 11;          // 0/1: which chunk of the pair
        const int pblk  = item & 2047;         // position block
        const int chunk = cpair * 2 + half;
        const int v0    = chunk * VC;
        const __half* slab = g_slab[half];

        const int pos = pblk * 8 + warp;
        const int b   = pos >> 11;             // / LL
        const int l   = pos & (LL - 1);        // % LL

        const uint4* r0; const uint4* r1; const uint4* r2; const uint4* r3;
        {
            int tok;
            tok = (l >= 3) ? __ldg(&idx[b * LL + l - 3]) : VV;
            r0 = reinterpret_cast<const uint4*>(slab + (size_t)(0 * (VV + 1) + tok) * VC);
            tok = (l >= 2) ? __ldg(&idx[b * LL + l - 2]) : VV;
            r1 = reinterpret_cast<const uint4*>(slab + (size_t)(1 * (VV + 1) + tok) * VC);
            tok = (l >= 1) ? __ldg(&idx[b * LL + l - 1]) : VV;
            r2 = reinterpret_cast<const uint4*>(slab + (size_t)(2 * (VV + 1) + tok) * VC);
            tok = __ldg(&idx[b * LL + l]);
            r3 = reinterpret_cast<const uint4*>(slab + (size_t)(3 * (VV + 1) + tok) * VC);
        }

        float4* o4 = reinterpret_cast<float4*>(out + (size_t)pos * VV + v0);

        // VC/8 = 128 uint4 items per slab row / 32 lanes = 4 iterations.
        #pragma unroll
        for (int i = 0; i < VC / 8 / 32; i++) {
            const int j = lane + i * 32;

            const uint4 h0 = r0[j];
            const uint4 h1 = r1[j];
            const uint4 h2 = r2[j];
            const uint4 h3 = r3[j];
            const __half2* q0 = reinterpret_cast<const __half2*>(&h0);
            const __half2* q1 = reinterpret_cast<const __half2*>(&h1);
            const __half2* q2 = reinterpret_cast<const __half2*>(&h2);
            const __half2* q3 = reinterpret_cast<const __half2*>(&h3);

            float4 oA, oB;
            {
                const float2 a0 = __half22float2(__hadd2(q0[0], q1[0]));
                const float2 b0 = __half22float2(__hadd2(q2[0], q3[0]));
                const float2 a1 = __half22float2(__hadd2(q0[1], q1[1]));
                const float2 b1 = __half22float2(__hadd2(q2[1], q3[1]));
                oA.x = a0.x + b0.x;  oA.y = a0.y + b0.y;
                oA.z = a1.x + b1.x;  oA.w = a1.y + b1.y;
                const float2 a2 = __half22float2(__hadd2(q0[2], q1[2]));
                const float2 b2 = __half22float2(__hadd2(q2[2], q3[2]));
                const float2 a3 = __half22float2(__hadd2(q0[3], q1[3]));
                const float2 b3 = __half22float2(__hadd2(q2[3], q3[3]));
                oB.x = a2.x + b2.x;  oB.y = a2.y + b2.y;
                oB.z = a3.x + b3.x;  oB.w = a3.y + b3.y;
            }
            __stcs(&o4[2 * j],     oA);     // streaming: don't evict the slabs
            __stcs(&o4[2 * j + 1], oB);
        }
    }
}

// ---------------------------------------------------------------------------
// Launch: 4 launches total — T(0,1), G(0,1), T(2,3), G(2,3).
// Inputs identified by element count:
//   idx : B*L = 16384 (int32), bias : V = 4096, W : V*FAN (largest)
// ---------------------------------------------------------------------------
extern "C" void kernel_launch(void* const* d_in, const int* in_sizes, int n_in,
                              void* d_out, int out_size) {
    const int*   idx  = nullptr;
    const float* W    = nullptr;
    const float* bias = nullptr;

    for (int i = 0; i < n_in; i++) {
        if (in_sizes[i] == NPOS)      idx  = (const int*)d_in[i];
        else if (in_sizes[i] == VV)   bias = (const float*)d_in[i];
        else                          W    = (const float*)d_in[i];
    }

    dim3 tblock(8, 32);
    dim3 tgrid(CMAIN / CT + 1, VC / 32, 2);   // (129, 32, 2)

    for (int cp = 0; cp < NCH / 2; cp++) {
        ngram_transpose_pair<<<tgrid, tblock>>>(W, bias, cp);
        ngram_gather_pair<<<GGRID, 256>>>(idx, (float*)d_out, cp);
    }
}

// round 13
// speedup vs baseline: 1.0926x; 1.0926x over previous
#include <cuda_runtime.h>
#include <cuda_fp16.h>

// Problem constants (fixed by the reference)
#define VV   4096                 // vocab
#define MM   4                    // markov order
#define BB   8
#define LL   2048
#define FAN  (MM * (VV + 1))      // 16388
#define NPOS (BB * LL)            // 16384

#define VC   1024                 // vocab chunk; one slab = FAN*VC*2B = 33.5 MB
#define NCH  (VV / VC)            // 4 chunks

#define NSUB 4                    // subtiles per transpose block (along fan_in)
#define CT   (NSUB * 32)          // 128 fan_in columns per block
#define CMAIN 16384               // fan_in covered by main transpose tiles

#define NTB  (129 * 32)           // transpose blocks per chunk = 4128
#define NGB  (NPOS / 8)           // gather blocks per chunk   = 2048
// Mixed-launch interleave: pattern [G,T,T] x 2048 = 6144 blocks, then the
// remaining 32 transpose blocks. Total mixed grid = 6176.
#define MIXED_GRID (3 * NGB + (NTB - 2 * NGB))

// Two slabs, ping-ponged by chunk parity. Within one mixed launch,
// G(c) reads g_slab[c&1] while T(c+1) writes g_slab[(c+1)&1] -- disjoint.
// Table-0 rows carry the fp32 bias folded in before fp16 quantization.
__device__ __half g_slab[2][(size_t)FAN * VC];

// ---------------------------------------------------------------------------
// Fused heterogeneous kernel. Each block takes ONE role:
//   transpose block: produce a 32v x 128c piece of slab[tchunk&1]
//   gather block   : consume slab[gchunk&1] for 8 positions
// Roles are interleaved in bid order (1 gather : 2 transpose) so both types
// are resident on every SM for the whole launch -> DRAM-bound transpose work
// overlaps L2-bound gather work.
//   gchunk <  0   : pure transpose launch (grid = NTB)
//   tchunk >= NCH : pure gather launch    (grid = NGB)
//   otherwise     : mixed                 (grid = MIXED_GRID)
// ---------------------------------------------------------------------------
__global__ __launch_bounds__(256, 6)
void ngram_fused(const float* __restrict__ W,
                 const float* __restrict__ bias,
                 const int*   __restrict__ idx,
                 float*       __restrict__ out,
                 int gchunk, int tchunk) {
    __shared__ float tile[NSUB][32][33];   // used by transpose blocks only

    const int t = threadIdx.x;

    // ---- role assignment ---------------------------------------------------
    int gitem = -1, titem = -1;
    if (gchunk < 0) {
        titem = blockIdx.x;                       // pure transpose
    } else if (tchunk >= NCH) {
        gitem = blockIdx.x;                       // pure gather
    } else {
        const int bid = blockIdx.x;
        if (bid < 3 * NGB) {
            const int q = bid / 3, r = bid - 3 * q;
            if (r == 0) gitem = q;                // every 3rd block gathers
            else        titem = q * 2 + (r - 1);
        } else {
            titem = 2 * NGB + (bid - 3 * NGB);    // trailing transpose blocks
        }
    }

    // ---- transpose role ----------------------------------------------------
    if (titem >= 0) {
        const int bx = titem % 129;               // fan tile (128 main + 1 rem)
        const int by = titem / 129;               // vocab tile within chunk
        const int v0 = tchunk * VC;
        __half* slab = g_slab[tchunk & 1];
        const int tx = t & 7;                     // 0..7
        const int ty = t >> 3;                    // 0..31

        if (bx == CMAIN / CT) {
            // Remainder fan rows cc = 16384..16387 (table 3: no bias).
            if (t < 4 * 32) {
                const int r  = t >> 5;            // 0..3
                const int v  = t & 31;
                const int vl = by * 32 + v;
                slab[(size_t)(CMAIN + r) * VC + vl] =
                    __float2half_rn(W[(size_t)(v0 + vl) * FAN + CMAIN + r]);
            }
            return;
        }

        const int c0  = bx * CT;                  // fan_in origin
        const int vl0 = by * 32;                  // local vocab origin

        // Load phase: 4 independent float4 streaming reads, scalar smem writes.
        float4 w4[NSUB];
        const float4* wrow = reinterpret_cast<const float4*>(
            &W[(size_t)(v0 + vl0 + ty) * FAN + c0 + tx * 4]);
        #pragma unroll
        for (int s = 0; s < NSUB; s++)
            w4[s] = __ldcs(wrow + s * 8);         // evict-first: protect slabs
        #pragma unroll
        for (int s = 0; s < NSUB; s++) {
            tile[s][ty][tx * 4 + 0] = w4[s].x;
            tile[s][ty][tx * 4 + 1] = w4[s].y;
            tile[s][ty][tx * 4 + 2] = w4[s].z;
            tile[s][ty][tx * 4 + 3] = w4[s].w;
        }
        __syncthreads();

        // Store phase: scalar smem reads, bias fold (exact fp32), cvt fp16,
        // 8-byte slab writes (write-back -> dirty lines live in L2).
        const bool foldblk = (c0 < VV + 1);
        float4 bb = make_float4(0.f, 0.f, 0.f, 0.f);
        if (foldblk)
            bb = *reinterpret_cast<const float4*>(&bias[v0 + vl0 + tx * 4]);

        #pragma unroll
        for (int s = 0; s < NSUB; s++) {
            const int cc = c0 + s * 32 + ty;
            float x0 = tile[s][tx * 4 + 0][ty];
            float x1 = tile[s][tx * 4 + 1][ty];
            float x2 = tile[s][tx * 4 + 2][ty];
            float x3 = tile[s][tx * 4 + 3][ty];
            if (foldblk && cc < VV + 1) {         // table 0: fold bias
                x0 += bb.x; x1 += bb.y; x2 += bb.z; x3 += bb.w;
            }
            const __half2 p0 = __floats2half2_rn(x0, x1);
            const __half2 p1 = __floats2half2_rn(x2, x3);
            uint2 o;
            o.x = *reinterpret_cast<const unsigned int*>(&p0);
            o.y = *reinterpret_cast<const unsigned int*>(&p1);
            *reinterpret_cast<uint2*>(&slab[(size_t)cc * VC + vl0 + tx * 4]) = o;
        }
        return;
    }

    // ---- gather role -------------------------------------------------------
    {
        const int v0 = gchunk * VC;
        const __half* slab = g_slab[gchunk & 1];
        const int warp = t >> 5;
        const int lane = t & 31;

        const int pos = gitem * 8 + warp;
        const int b   = pos >> 11;                // / LL
        const int l   = pos & (LL - 1);           // % LL

        const uint4* r0; const uint4* r1; const uint4* r2; const uint4* r3;
        {
            int tok;
            tok = (l >= 3) ? __ldg(&idx[b * LL + l - 3]) : VV;
            r0 = reinterpret_cast<const uint4*>(slab + (size_t)(0 * (VV + 1) + tok) * VC);
            tok = (l >= 2) ? __ldg(&idx[b * LL + l - 2]) : VV;
            r1 = reinterpret_cast<const uint4*>(slab + (size_t)(1 * (VV + 1) + tok) * VC);
            tok = (l >= 1) ? __ldg(&idx[b * LL + l - 1]) : VV;
            r2 = reinterpret_cast<const uint4*>(slab + (size_t)(2 * (VV + 1) + tok) * VC);
            tok = __ldg(&idx[b * LL + l]);
            r3 = reinterpret_cast<const uint4*>(slab + (size_t)(3 * (VV + 1) + tok) * VC);
        }

        float4* o4 = reinterpret_cast<float4*>(out + (size_t)pos * VV + v0);

        // VC/8 = 128 uint4 items per slab row / 32 lanes = 4 iterations.
        #pragma unroll
        for (int i = 0; i < VC / 8 / 32; i++) {
            const int j = lane + i * 32;

            const uint4 h0 = r0[j];
            const uint4 h1 = r1[j];
            const uint4 h2 = r2[j];
            const uint4 h3 = r3[j];
            const __half2* q0 = reinterpret_cast<const __half2*>(&h0);
            const __half2* q1 = reinterpret_cast<const __half2*>(&h1);
            const __half2* q2 = reinterpret_cast<const __half2*>(&h2);
            const __half2* q3 = reinterpret_cast<const __half2*>(&h3);

            float4 oA, oB;
            {
                // Pairwise fp16 adds (HADD2), finish in fp32.
                const float2 a0 = __half22float2(__hadd2(q0[0], q1[0]));
                const float2 b0 = __half22float2(__hadd2(q2[0], q3[0]));
                const float2 a1 = __half22float2(__hadd2(q0[1], q1[1]));
                const float2 b1 = __half22float2(__hadd2(q2[1], q3[1]));
                oA.x = a0.x + b0.x;  oA.y = a0.y + b0.y;
                oA.z = a1.x + b1.x;  oA.w = a1.y + b1.y;
                const float2 a2 = __half22float2(__hadd2(q0[2], q1[2]));
                const float2 b2 = __half22float2(__hadd2(q2[2], q3[2]));
                const float2 a3 = __half22float2(__hadd2(q0[3], q1[3]));
                const float2 b3 = __half22float2(__hadd2(q2[3], q3[3]));
                oB.x = a2.x + b2.x;  oB.y = a2.y + b2.y;
                oB.z = a3.x + b3.x;  oB.w = a3.y + b3.y;
            }
            __stcs(&o4[2 * j],     oA);           // streaming: protect slabs
            __stcs(&o4[2 * j + 1], oB);
        }
    }
}

// ---------------------------------------------------------------------------
// Launch: 5-stage software pipeline
//   T(0) | G(0)+T(1) | G(1)+T(2) | G(2)+T(3) | G(3)
// Inputs identified by element count:
//   idx : B*L = 16384 (int32), bias : V = 4096, W : V*FAN (largest)
// ---------------------------------------------------------------------------
extern "C" void kernel_launch(void* const* d_in, const int* in_sizes, int n_in,
                              void* d_out, int out_size) {
    const int*   idx  = nullptr;
    const float* W    = nullptr;
    const float* bias = nullptr;

    for (int i = 0; i < n_in; i++) {
        if (in_sizes[i] == NPOS)      idx  = (const int*)d_in[i];
        else if (in_sizes[i] == VV)   bias = (const float*)d_in[i];
        else                          W    = (const float*)d_in[i];
    }

    float* out = (float*)d_out;

    for (int phase = 0; phase <= NCH; phase++) {
        const int gchunk = phase - 1;
        const int tchunk = phase;
        int grid;
        if (phase == 0)         grid = NTB;         // pure transpose
        else if (phase == NCH)  grid = NGB;         // pure gather
        else                    grid = MIXED_GRID;  // interleaved G + T
        ngram_fused<<<grid, 256>>>(W, bias, idx, out, gchunk, tchunk);
    }
}